// round 1
// baseline (speedup 1.0000x reference)
#include <cuda_runtime.h>
#include <cstdint>

// Problem constants
#define Nn 20000
#define Ee 320000
#define Bb 2
#define INF_DIM 32
#define HIDD 64
#define HEADS 4
#define OUTD 8
#define SLOPE 0.2f

#define NB (Nn*Bb)              // 40000
#define FTC (HEADS*HIDD)        // 256

// Scratch (device globals; zero-initialized at load; agg re-zeroed by update kernel each round)
__device__ __align__(16) float g_x[NB*HIDD];
__device__ __align__(16) float g_ft[(size_t)NB*FTC];
__device__ __align__(16) float g_agg[(size_t)NB*FTC];
__device__ __align__(16) float g_res[NB*HIDD];
__device__ float g_el[NB*HEADS];
__device__ float g_er[NB*HEADS];
__device__ float g_m[NB*HEADS];
__device__ float g_z[NB*HEADS];

__device__ __forceinline__ void atomicMaxFloat(float* addr, float value) {
    if (value >= 0.0f) {
        atomicMax((int*)addr, __float_as_int(value));
    } else {
        atomicMin((unsigned int*)addr, __float_as_uint(value));
    }
}

__device__ __forceinline__ void red_add_v4(float* addr, float4 v) {
    asm volatile("red.global.add.v4.f32 [%0], {%1,%2,%3,%4};"
                 :: "l"(addr), "f"(v.x), "f"(v.y), "f"(v.z), "f"(v.w) : "memory");
}

// ---------------- encoder: x[n,b,:] = h[b,n,:] @ W_enc + b_enc ----------------
__global__ void enc_k(const float* __restrict__ h, const float* __restrict__ W_enc,
                      const float* __restrict__ b_enc) {
    int idx = blockIdx.x * blockDim.x + threadIdx.x;
    if (idx >= NB*HIDD) return;
    int d  = idx & 63;
    int nb = idx >> 6;
    int n = nb >> 1, b = nb & 1;
    const float* hr = &h[((size_t)b*Nn + n)*INF_DIM];
    float acc = b_enc[d];
#pragma unroll
    for (int k = 0; k < INF_DIM; k++) acc += hr[k] * W_enc[k*HIDD + d];
    g_x[idx] = acc;
}

// ---------------- ft = x @ W_gat (+ fused el/er) ----------------
// block: 256 threads, 8 rows of x per block. thread t owns output column t.
__global__ void ft_k(const float* __restrict__ W_gat, const float* __restrict__ a_l,
                     const float* __restrict__ a_r) {
    __shared__ float xs[8][HIDD];
    __shared__ float els[8][HEADS];
    __shared__ float ers[8][HEADS];
    int t = threadIdx.x;
    int nb0 = blockIdx.x * 8;

    for (int i = t; i < 8*HIDD; i += 256)
        xs[i >> 6][i & 63] = g_x[(size_t)nb0*HIDD + i];
    if (t < 32) { els[t >> 2][t & 3] = 0.f; ers[t >> 2][t & 3] = 0.f; }
    __syncthreads();

    float acc[8];
#pragma unroll
    for (int r = 0; r < 8; r++) acc[r] = 0.f;

    for (int k = 0; k < HIDD; k++) {
        float wv = W_gat[k*FTC + t];
#pragma unroll
        for (int r = 0; r < 8; r++) acc[r] += xs[r][k] * wv;
    }

    float al = a_l[t];   // a_l flattened [HEADS,HID] matches column index t = h*64+d
    float ar = a_r[t];
    int hh = t >> 6;
#pragma unroll
    for (int r = 0; r < 8; r++) {
        g_ft[((size_t)(nb0 + r))*FTC + t] = acc[r];
        float pl = acc[r] * al;
        float pr = acc[r] * ar;
#pragma unroll
        for (int o = 16; o > 0; o >>= 1) {
            pl += __shfl_xor_sync(0xffffffffu, pl, o);
            pr += __shfl_xor_sync(0xffffffffu, pr, o);
        }
        if ((t & 31) == 0) {
            atomicAdd(&els[r][hh], pl);
            atomicAdd(&ers[r][hh], pr);
        }
    }
    __syncthreads();
    if (t < 32) {
        int r = t >> 2, h2 = t & 3;
        g_el[(nb0 + r)*HEADS + h2] = els[r][h2];
        g_er[(nb0 + r)*HEADS + h2] = ers[r][h2];
    }
}

// ---------------- res = x @ W_res + b_res ----------------
// block: 256 threads, 4 rows per block. thread: r = t/64, c = t%64.
__global__ void res_k(const float* __restrict__ W_res, const float* __restrict__ b_res) {
    __shared__ float xs[4][HIDD];
    int t = threadIdx.x;
    int nb0 = blockIdx.x * 4;
    for (int i = t; i < 4*HIDD; i += 256)
        xs[i >> 6][i & 63] = g_x[(size_t)nb0*HIDD + i];
    __syncthreads();
    int r = t >> 6, c = t & 63;
    float acc = b_res[c];
    for (int k = 0; k < HIDD; k++) acc += xs[r][k] * W_res[k*HIDD + c];
    g_res[(size_t)(nb0 + r)*HIDD + c] = acc;
}

// ---------------- init m/z per round ----------------
__global__ void init_k() {
    int idx = blockIdx.x * blockDim.x + threadIdx.x;
    if (idx >= NB*HEADS) return;
    g_m[idx] = __int_as_float(0xff800000);  // -inf
    g_z[idx] = 0.f;
}

// ---------------- edge pass 1: segment max ----------------
__global__ void edge_max_k(const int* __restrict__ ei) {
    int idx = blockIdx.x * blockDim.x + threadIdx.x;
    if (idx >= Ee*Bb*HEADS) return;
    int e = idx >> 3;
    int rem = idx & 7;          // b*4 + h
    int s = ei[e], d = ei[Ee + e];
    float v = g_el[s*8 + rem] + g_er[d*8 + rem];
    v = v > 0.f ? v : SLOPE * v;
    atomicMaxFloat(&g_m[d*8 + rem], v);
}

// ---------------- edge pass 2: exp-sum ----------------
__global__ void edge_sum_k(const int* __restrict__ ei) {
    int idx = blockIdx.x * blockDim.x + threadIdx.x;
    if (idx >= Ee*Bb*HEADS) return;
    int e = idx >> 3;
    int rem = idx & 7;
    int s = ei[e], d = ei[Ee + e];
    float v = g_el[s*8 + rem] + g_er[d*8 + rem];
    v = v > 0.f ? v : SLOPE * v;
    float ex = __expf(v - g_m[d*8 + rem]);
    atomicAdd(&g_z[d*8 + rem], ex);
}

// ---------------- edge pass 3: weighted aggregation ----------------
// one warp per (edge, batch): 256 floats = 2 float4 per lane, red.v4 scatter
__global__ void edge_agg_k(const int* __restrict__ ei) {
    int w = (blockIdx.x * blockDim.x + threadIdx.x) >> 5;
    int lane = threadIdx.x & 31;
    if (w >= Ee*Bb) return;
    int e = w >> 1;
    int b = w & 1;
    int s = ei[e], d = ei[Ee + e];

    int base_s = s*8 + b*4;
    int base_d = d*8 + b*4;
    float alpha[HEADS];
#pragma unroll
    for (int h = 0; h < HEADS; h++) {
        float v = g_el[base_s + h] + g_er[base_d + h];
        v = v > 0.f ? v : SLOPE * v;
        alpha[h] = __expf(v - g_m[base_d + h]) / g_z[base_d + h];
    }

    const float4* ftp = (const float4*)&g_ft[((size_t)s*Bb + b)*FTC];
    float* aggp = &g_agg[((size_t)d*Bb + b)*FTC];

    float4 v0 = ftp[lane];        // cols [lane*4, lane*4+4) -> head lane/16
    float4 v1 = ftp[lane + 32];   // cols 128 + lane*4       -> head 2+lane/16
    float a0 = alpha[lane >> 4];
    float a1 = alpha[2 + (lane >> 4)];
    v0.x *= a0; v0.y *= a0; v0.z *= a0; v0.w *= a0;
    v1.x *= a1; v1.y *= a1; v1.z *= a1; v1.w *= a1;
    red_add_v4(aggp + lane*4, v0);
    red_add_v4(aggp + 128 + lane*4, v1);
}

// ---------------- update: x = elu(mean_h(agg)+mean_h(b_gat)+res); agg := 0 ----------------
__global__ void update_k(const float* __restrict__ b_gat) {
    int idx = blockIdx.x * blockDim.x + threadIdx.x;
    if (idx >= NB*HIDD) return;
    int d = idx & 63;
    size_t nb = (size_t)(idx >> 6);
    float* ap = &g_agg[nb*FTC];
    float s = 0.25f * (ap[d] + ap[64 + d] + ap[128 + d] + ap[192 + d]);
    ap[d] = 0.f; ap[64 + d] = 0.f; ap[128 + d] = 0.f; ap[192 + d] = 0.f;
    float bg = 0.25f * (b_gat[d] + b_gat[64 + d] + b_gat[128 + d] + b_gat[192 + d]);
    float v = s + bg + g_res[idx];
    g_x[idx] = v > 0.f ? v : expm1f(v);
}

// ---------------- decoder: out[b,n,:] = x[n,b,:] @ W_dec + b_dec ----------------
__global__ void dec_k(const float* __restrict__ W_dec, const float* __restrict__ b_dec,
                      float* __restrict__ out) {
    int idx = blockIdx.x * blockDim.x + threadIdx.x;
    if (idx >= NB*OUTD) return;
    int o = idx & 7;
    int nb = idx >> 3;
    int n = nb >> 1, b = nb & 1;
    const float* xr = &g_x[(size_t)nb*HIDD];
    float acc = b_dec[o];
#pragma unroll
    for (int k = 0; k < HIDD; k++) acc += xr[k] * W_dec[k*OUTD + o];
    out[((size_t)b*Nn + n)*OUTD + o] = acc;
}

extern "C" void kernel_launch(void* const* d_in, const int* in_sizes, int n_in,
                              void* d_out, int out_size) {
    const float* h     = (const float*)d_in[0];
    const int*   ei    = (const int*)  d_in[1];
    const float* W_enc = (const float*)d_in[2];
    const float* b_enc = (const float*)d_in[3];
    const float* W_gat = (const float*)d_in[4];
    const float* a_l   = (const float*)d_in[5];
    const float* a_r   = (const float*)d_in[6];
    const float* b_gat = (const float*)d_in[7];
    const float* W_res = (const float*)d_in[8];
    const float* b_res = (const float*)d_in[9];
    const float* W_dec = (const float*)d_in[10];
    const float* b_dec = (const float*)d_in[11];
    float* out = (float*)d_out;

    enc_k<<<(NB*HIDD + 255)/256, 256>>>(h, W_enc, b_enc);

    for (int it = 0; it < 2; ++it) {
        init_k<<<(NB*HEADS + 255)/256, 256>>>();
        ft_k<<<NB/8, 256>>>(W_gat, a_l, a_r);
        res_k<<<NB/4, 256>>>(W_res, b_res);
        edge_max_k<<<(Ee*Bb*HEADS + 255)/256, 256>>>(ei);
        edge_sum_k<<<(Ee*Bb*HEADS + 255)/256, 256>>>(ei);
        edge_agg_k<<<(Ee*Bb*32 + 255)/256, 256>>>(ei);
        update_k<<<(NB*HIDD + 255)/256, 256>>>(b_gat);
    }

    dec_k<<<(NB*OUTD + 255)/256, 256>>>(W_dec, b_dec, out);
}

// round 2
// speedup vs baseline: 1.4158x; 1.4158x over previous
#include <cuda_runtime.h>
#include <cstdint>

// Problem constants
#define Nn 20000
#define Ee 320000
#define Bb 2
#define INF_DIM 32
#define HIDD 64
#define HEADS 4
#define OUTD 8
#define SLOPE 0.2f

#define NB (Nn*Bb)              // 40000
#define FTC (HEADS*HIDD)        // 256

// Scratch (device globals; zero-initialized at load; agg64 re-zeroed by update kernel each round)
__device__ __align__(16) float g_x[NB*HIDD];
__device__ __align__(16) float g_ft[(size_t)NB*FTC];
__device__ __align__(16) float g_agg64[(size_t)NB*HIDD];
__device__ __align__(16) float g_res[NB*HIDD];
__device__ float g_el[NB*HEADS];
__device__ float g_er[NB*HEADS];
__device__ float g_m[NB*HEADS];
__device__ float g_z[NB*HEADS];

__device__ __forceinline__ void atomicMaxFloat(float* addr, float value) {
    if (value >= 0.0f) {
        atomicMax((int*)addr, __float_as_int(value));
    } else {
        atomicMin((unsigned int*)addr, __float_as_uint(value));
    }
}

// ---------------- encoder: x[n,b,:] = h[b,n,:] @ W_enc + b_enc ----------------
__global__ void enc_k(const float* __restrict__ h, const float* __restrict__ W_enc,
                      const float* __restrict__ b_enc) {
    int idx = blockIdx.x * blockDim.x + threadIdx.x;
    if (idx >= NB*HIDD) return;
    int d  = idx & 63;
    int nb = idx >> 6;
    int n = nb >> 1, b = nb & 1;
    const float* hr = &h[((size_t)b*Nn + n)*INF_DIM];
    float acc = b_enc[d];
#pragma unroll
    for (int k = 0; k < INF_DIM; k++) acc += hr[k] * W_enc[k*HIDD + d];
    g_x[idx] = acc;
}

// ---------------- ft = x @ W_gat (+ fused el/er, res = x @ W_res + b_res, m/z init) ----------------
// block: 256 threads, 8 rows of x per block. thread t owns ft output column t.
__global__ void ft_k(const float* __restrict__ W_gat, const float* __restrict__ a_l,
                     const float* __restrict__ a_r,
                     const float* __restrict__ W_res, const float* __restrict__ b_res) {
    __shared__ float xs[8][HIDD];
    __shared__ float els[8][HEADS];
    __shared__ float ers[8][HEADS];
    int t = threadIdx.x;
    int nb0 = blockIdx.x * 8;

    for (int i = t; i < 8*HIDD; i += 256)
        xs[i >> 6][i & 63] = g_x[(size_t)nb0*HIDD + i];
    if (t < 32) {
        els[t >> 2][t & 3] = 0.f; ers[t >> 2][t & 3] = 0.f;
        // init segment-softmax state for the upcoming edge passes
        g_m[nb0*HEADS + t] = __int_as_float(0xff800000);  // -inf
        g_z[nb0*HEADS + t] = 0.f;
    }
    __syncthreads();

    float acc[8];
#pragma unroll
    for (int r = 0; r < 8; r++) acc[r] = 0.f;

    for (int k = 0; k < HIDD; k++) {
        float wv = W_gat[k*FTC + t];
#pragma unroll
        for (int r = 0; r < 8; r++) acc[r] += xs[r][k] * wv;
    }

    float al = a_l[t];   // a_l flattened [HEADS,HID] matches column index t = h*64+d
    float ar = a_r[t];
    int hh = t >> 6;
#pragma unroll
    for (int r = 0; r < 8; r++) {
        g_ft[((size_t)(nb0 + r))*FTC + t] = acc[r];
        float pl = acc[r] * al;
        float pr = acc[r] * ar;
#pragma unroll
        for (int o = 16; o > 0; o >>= 1) {
            pl += __shfl_xor_sync(0xffffffffu, pl, o);
            pr += __shfl_xor_sync(0xffffffffu, pr, o);
        }
        if ((t & 31) == 0) {
            atomicAdd(&els[r][hh], pl);
            atomicAdd(&ers[r][hh], pr);
        }
    }

    // res = x @ W_res + b_res : thread t computes col c for rows rr and rr+4
    {
        int c = t & 63, rr = t >> 6;
        float r0 = b_res[c];
        float r1 = r0;
        for (int k = 0; k < HIDD; k++) {
            float wv = W_res[k*HIDD + c];
            r0 += xs[rr][k] * wv;
            r1 += xs[rr + 4][k] * wv;
        }
        g_res[(size_t)(nb0 + rr)*HIDD + c] = r0;
        g_res[(size_t)(nb0 + rr + 4)*HIDD + c] = r1;
    }

    __syncthreads();
    if (t < 32) {
        int r = t >> 2, h2 = t & 3;
        g_el[(nb0 + r)*HEADS + h2] = els[r][h2];
        g_er[(nb0 + r)*HEADS + h2] = ers[r][h2];
    }
}

// ---------------- edge pass 1: segment max ----------------
__global__ void edge_max_k(const int* __restrict__ ei) {
    int idx = blockIdx.x * blockDim.x + threadIdx.x;
    if (idx >= Ee*Bb*HEADS) return;
    int e = idx >> 3;
    int rem = idx & 7;          // b*4 + h
    int s = ei[e], d = ei[Ee + e];
    float v = g_el[s*8 + rem] + g_er[d*8 + rem];
    v = v > 0.f ? v : SLOPE * v;
    atomicMaxFloat(&g_m[d*8 + rem], v);
}

// ---------------- edge pass 2: exp-sum ----------------
__global__ void edge_sum_k(const int* __restrict__ ei) {
    int idx = blockIdx.x * blockDim.x + threadIdx.x;
    if (idx >= Ee*Bb*HEADS) return;
    int e = idx >> 3;
    int rem = idx & 7;
    int s = ei[e], d = ei[Ee + e];
    float v = g_el[s*8 + rem] + g_er[d*8 + rem];
    v = v > 0.f ? v : SLOPE * v;
    float ex = __expf(v - g_m[d*8 + rem]);
    atomicAdd(&g_z[d*8 + rem], ex);
}

// ---------------- edge pass 3: weighted aggregation (head-reduced) ----------------
// one warp per edge, both batches. alpha computed once per warp (lanes 0-7), shuffled.
// lane owns output dims [lane*2, lane*2+2); accumulates 0.25 * sum_h alpha_h * ft over heads
// in registers, then a single red.v2 per batch into agg64[dst][b][64].
__global__ void edge_agg_k(const int* __restrict__ ei) {
    int w = (blockIdx.x * blockDim.x + threadIdx.x) >> 5;
    int lane = threadIdx.x & 31;
    if (w >= Ee) return;
    int s = ei[w], d = ei[Ee + w];

    float aval = 0.f;
    if (lane < 8) {
        int b = lane >> 2, h = lane & 3;
        int is = (s*2 + b)*HEADS + h;
        int id = (d*2 + b)*HEADS + h;
        float v = g_el[is] + g_er[id];
        v = v > 0.f ? v : SLOPE * v;
        aval = 0.25f * __expf(v - g_m[id]) / g_z[id];
    }
    float al[2][4];
#pragma unroll
    for (int b = 0; b < 2; b++)
#pragma unroll
        for (int h = 0; h < 4; h++)
            al[b][h] = __shfl_sync(0xffffffffu, aval, b*4 + h);

#pragma unroll
    for (int b = 0; b < 2; b++) {
        const float2* fp = (const float2*)&g_ft[((size_t)(s*2 + b))*FTC];
        float2 acc = make_float2(0.f, 0.f);
#pragma unroll
        for (int h = 0; h < 4; h++) {
            float2 v = fp[h*32 + lane];
            acc.x += al[b][h] * v.x;
            acc.y += al[b][h] * v.y;
        }
        float* ap = &g_agg64[((size_t)(d*2 + b))*HIDD + lane*2];
        asm volatile("red.global.add.v2.f32 [%0], {%1,%2};"
                     :: "l"(ap), "f"(acc.x), "f"(acc.y) : "memory");
    }
}

// ---------------- update: x = elu(agg64 + mean_h(b_gat) + res); agg64 := 0 ----------------
__global__ void update_k(const float* __restrict__ b_gat) {
    int idx = blockIdx.x * blockDim.x + threadIdx.x;
    if (idx >= NB*HIDD) return;
    int d = idx & 63;
    float s = g_agg64[idx];
    g_agg64[idx] = 0.f;
    float bg = 0.25f * (b_gat[d] + b_gat[64 + d] + b_gat[128 + d] + b_gat[192 + d]);
    float v = s + bg + g_res[idx];
    g_x[idx] = v > 0.f ? v : expm1f(v);
}

// ---------------- decoder: out[b,n,:] = x[n,b,:] @ W_dec + b_dec ----------------
__global__ void dec_k(const float* __restrict__ W_dec, const float* __restrict__ b_dec,
                      float* __restrict__ out) {
    int idx = blockIdx.x * blockDim.x + threadIdx.x;
    if (idx >= NB*OUTD) return;
    int o = idx & 7;
    int nb = idx >> 3;
    int n = nb >> 1, b = nb & 1;
    const float* xr = &g_x[(size_t)nb*HIDD];
    float acc = b_dec[o];
#pragma unroll
    for (int k = 0; k < HIDD; k++) acc += xr[k] * W_dec[k*OUTD + o];
    out[((size_t)b*Nn + n)*OUTD + o] = acc;
}

extern "C" void kernel_launch(void* const* d_in, const int* in_sizes, int n_in,
                              void* d_out, int out_size) {
    const float* h     = (const float*)d_in[0];
    const int*   ei    = (const int*)  d_in[1];
    const float* W_enc = (const float*)d_in[2];
    const float* b_enc = (const float*)d_in[3];
    const float* W_gat = (const float*)d_in[4];
    const float* a_l   = (const float*)d_in[5];
    const float* a_r   = (const float*)d_in[6];
    const float* b_gat = (const float*)d_in[7];
    const float* W_res = (const float*)d_in[8];
    const float* b_res = (const float*)d_in[9];
    const float* W_dec = (const float*)d_in[10];
    const float* b_dec = (const float*)d_in[11];
    float* out = (float*)d_out;

    enc_k<<<(NB*HIDD + 255)/256, 256>>>(h, W_enc, b_enc);

    for (int it = 0; it < 2; ++it) {
        ft_k<<<NB/8, 256>>>(W_gat, a_l, a_r, W_res, b_res);
        edge_max_k<<<(Ee*Bb*HEADS + 255)/256, 256>>>(ei);
        edge_sum_k<<<(Ee*Bb*HEADS + 255)/256, 256>>>(ei);
        edge_agg_k<<<(Ee*32 + 255)/256, 256>>>(ei);
        update_k<<<(NB*HIDD + 255)/256, 256>>>(b_gat);
    }

    dec_k<<<(NB*OUTD + 255)/256, 256>>>(W_dec, b_dec, out);
}

// round 3
// speedup vs baseline: 1.6734x; 1.1820x over previous
#include <cuda_runtime.h>
#include <cstdint>

// Problem constants
#define Nn 20000
#define Ee 320000
#define Bb 2
#define INF_DIM 32
#define HIDD 64
#define HEADS 4
#define OUTD 8
#define SLOPE 0.2f

#define NB (Nn*Bb)              // 40000
#define FTC (HEADS*HIDD)        // 256

// Scratch (device globals; CSR counters re-zeroed each call by zero_k)
__device__ __align__(16) float g_x[NB*HIDD];
__device__ __align__(16) float g_ft[(size_t)NB*FTC];
__device__ __align__(16) float g_res[NB*HIDD];
__device__ float g_el[NB*HEADS];   // [node*8 + b*4 + h]
__device__ float g_er[NB*HEADS];
__device__ int g_deg[Nn];
__device__ int g_fill[Nn];
__device__ int g_rowptr[Nn + 1];
__device__ int g_col[Ee];

// ---------------- CSR build ----------------
__global__ void zero_k() {
    int idx = blockIdx.x * blockDim.x + threadIdx.x;
    if (idx < Nn) { g_deg[idx] = 0; g_fill[idx] = 0; }
}

__global__ void hist_k(const int* __restrict__ ei) {
    int idx = blockIdx.x * blockDim.x + threadIdx.x;
    if (idx < Ee) atomicAdd(&g_deg[ei[Ee + idx]], 1);
}

// single-block exclusive scan of g_deg[0..Nn) -> g_rowptr
__global__ void scan_k() {
    __shared__ int wsum[32];
    __shared__ int woff[32];
    __shared__ int btot_s;
    int tid = threadIdx.x;
    int lane = tid & 31, wid = tid >> 5;
    int carry = 0;
    for (int base = 0; base < Nn; base += 1024) {
        int i = base + tid;
        int v = (i < Nn) ? g_deg[i] : 0;
        int incl = v;
#pragma unroll
        for (int o = 1; o < 32; o <<= 1) {
            int t = __shfl_up_sync(0xffffffffu, incl, o);
            if (lane >= o) incl += t;
        }
        if (lane == 31) wsum[wid] = incl;
        __syncthreads();
        if (tid < 32) {
            int wv = wsum[tid];
            int wincl = wv;
#pragma unroll
            for (int o = 1; o < 32; o <<= 1) {
                int t = __shfl_up_sync(0xffffffffu, wincl, o);
                if (tid >= o) wincl += t;
            }
            woff[tid] = wincl - wv;
            if (tid == 31) btot_s = wincl;
        }
        __syncthreads();
        if (i < Nn) g_rowptr[i] = carry + woff[wid] + (incl - v);
        int btot = btot_s;
        __syncthreads();
        carry += btot;
    }
    if (tid == 0) g_rowptr[Nn] = carry;
}

__global__ void fill_k(const int* __restrict__ ei) {
    int idx = blockIdx.x * blockDim.x + threadIdx.x;
    if (idx >= Ee) return;
    int d = ei[Ee + idx];
    int pos = g_rowptr[d] + atomicAdd(&g_fill[d], 1);
    g_col[pos] = ei[idx];
}

// ---------------- encoder: x[n,b,:] = h[b,n,:] @ W_enc + b_enc ----------------
__global__ void enc_k(const float* __restrict__ h, const float* __restrict__ W_enc,
                      const float* __restrict__ b_enc) {
    int idx = blockIdx.x * blockDim.x + threadIdx.x;
    if (idx >= NB*HIDD) return;
    int d  = idx & 63;
    int nb = idx >> 6;
    int n = nb >> 1, b = nb & 1;
    const float* hr = &h[((size_t)b*Nn + n)*INF_DIM];
    float acc = b_enc[d];
#pragma unroll
    for (int k = 0; k < INF_DIM; k++) acc += hr[k] * W_enc[k*HIDD + d];
    g_x[idx] = acc;
}

// ---------------- ft = x @ W_gat (+ fused el/er, res = x @ W_res + b_res) ----------------
// block: 256 threads, 16 rows of x. thread t owns ft output column t.
#define FTROWS 16
__global__ void ft_k(const float* __restrict__ W_gat, const float* __restrict__ a_l,
                     const float* __restrict__ a_r,
                     const float* __restrict__ W_res, const float* __restrict__ b_res) {
    __shared__ float xs[FTROWS][HIDD];
    __shared__ float els[FTROWS][HEADS];
    __shared__ float ers[FTROWS][HEADS];
    int t = threadIdx.x;
    int nb0 = blockIdx.x * FTROWS;

    for (int i = t; i < FTROWS*HIDD; i += 256)
        xs[i >> 6][i & 63] = g_x[(size_t)nb0*HIDD + i];
    if (t < FTROWS*HEADS) { els[t >> 2][t & 3] = 0.f; ers[t >> 2][t & 3] = 0.f; }
    __syncthreads();

    float acc[FTROWS];
#pragma unroll
    for (int r = 0; r < FTROWS; r++) acc[r] = 0.f;

    for (int k = 0; k < HIDD; k++) {
        float wv = W_gat[k*FTC + t];
#pragma unroll
        for (int r = 0; r < FTROWS; r++) acc[r] += xs[r][k] * wv;
    }

    float al = a_l[t];
    float ar = a_r[t];
    int hh = t >> 6;
#pragma unroll
    for (int r = 0; r < FTROWS; r++) {
        g_ft[((size_t)(nb0 + r))*FTC + t] = acc[r];
        float pl = acc[r] * al;
        float pr = acc[r] * ar;
#pragma unroll
        for (int o = 16; o > 0; o >>= 1) {
            pl += __shfl_xor_sync(0xffffffffu, pl, o);
            pr += __shfl_xor_sync(0xffffffffu, pr, o);
        }
        if ((t & 31) == 0) {
            atomicAdd(&els[r][hh], pl);
            atomicAdd(&ers[r][hh], pr);
        }
    }

    // res = x @ W_res + b_res : thread t computes col c for 4 rows
    {
        int c = t & 63, rr = t >> 6;
        float r0 = b_res[c], r1 = r0, r2 = r0, r3 = r0;
        for (int k = 0; k < HIDD; k++) {
            float wv = W_res[k*HIDD + c];
            r0 += xs[rr][k] * wv;
            r1 += xs[rr + 4][k] * wv;
            r2 += xs[rr + 8][k] * wv;
            r3 += xs[rr + 12][k] * wv;
        }
        g_res[(size_t)(nb0 + rr)*HIDD + c] = r0;
        g_res[(size_t)(nb0 + rr + 4)*HIDD + c] = r1;
        g_res[(size_t)(nb0 + rr + 8)*HIDD + c] = r2;
        g_res[(size_t)(nb0 + rr + 12)*HIDD + c] = r3;
    }

    __syncthreads();
    if (t < FTROWS*HEADS) {
        int r = t >> 2, h2 = t & 3;
        g_el[(nb0 + r)*HEADS + h2] = els[r][h2];
        g_er[(nb0 + r)*HEADS + h2] = ers[r][h2];
    }
}

// ---------------- fused node-centric GAT aggregation + update ----------------
// one warp per dst node; handles both batches. No atomics.
// x[d,b,:] = elu( mean_h( softmax-agg of ft[src,h,:] ) + mean_h(b_gat) + res[d,b,:] )
__global__ void node_agg_k(const float* __restrict__ b_gat) {
    int w = (blockIdx.x * blockDim.x + threadIdx.x) >> 5;
    int lane = threadIdx.x & 31;
    if (w >= Nn) return;
    int beg = g_rowptr[w], end = g_rowptr[w + 1];

    // broadcast er[w, b, h] (8 values) to all lanes
    float er_v = (lane < 8) ? g_er[w*8 + lane] : 0.f;
    float er_all[8];
#pragma unroll
    for (int j = 0; j < 8; j++) er_all[j] = __shfl_sync(0xffffffffu, er_v, j);

    // Pass A: per-(b,h) max over incoming edges
    float mx[8];
#pragma unroll
    for (int j = 0; j < 8; j++) mx[j] = -1e30f;
    for (int i = beg + lane; i < end; i += 32) {
        int s = g_col[i];
        const float* elp = &g_el[s*8];
#pragma unroll
        for (int j = 0; j < 8; j++) {
            float v = elp[j] + er_all[j];
            v = v > 0.f ? v : SLOPE * v;
            mx[j] = fmaxf(mx[j], v);
        }
    }
#pragma unroll
    for (int o = 16; o > 0; o >>= 1)
#pragma unroll
        for (int j = 0; j < 8; j++)
            mx[j] = fmaxf(mx[j], __shfl_xor_sync(0xffffffffu, mx[j], o));

    // Pass B: z = sum exp(v - m)
    float zz[8];
#pragma unroll
    for (int j = 0; j < 8; j++) zz[j] = 0.f;
    for (int i = beg + lane; i < end; i += 32) {
        int s = g_col[i];
        const float* elp = &g_el[s*8];
#pragma unroll
        for (int j = 0; j < 8; j++) {
            float v = elp[j] + er_all[j];
            v = v > 0.f ? v : SLOPE * v;
            zz[j] += __expf(v - mx[j]);
        }
    }
#pragma unroll
    for (int o = 16; o > 0; o >>= 1)
#pragma unroll
        for (int j = 0; j < 8; j++)
            zz[j] += __shfl_xor_sync(0xffffffffu, zz[j], o);
    float rz[8];
#pragma unroll
    for (int j = 0; j < 8; j++) rz[j] = 0.25f / zz[j];  // fold head-mean

    // Pass C: weighted gather; lane owns dims [lane*2, lane*2+2)
    float2 acc0 = make_float2(0.f, 0.f);
    float2 acc1 = make_float2(0.f, 0.f);
    for (int i = beg; i < end; i++) {
        int s = g_col[i];  // uniform across warp -> broadcast
        float a = 0.f;
        if (lane < 8) {
            float v = g_el[s*8 + lane] + er_all[lane];
            v = v > 0.f ? v : SLOPE * v;
            a = __expf(v - mx[lane]) * rz[lane];
        }
        float al[8];
#pragma unroll
        for (int j = 0; j < 8; j++) al[j] = __shfl_sync(0xffffffffu, a, j);

        const float2* f0 = (const float2*)&g_ft[((size_t)(s*2))*FTC];
        const float2* f1 = (const float2*)&g_ft[((size_t)(s*2 + 1))*FTC];
#pragma unroll
        for (int hq = 0; hq < 4; hq++) {
            float2 v0 = f0[hq*32 + lane];
            float2 v1 = f1[hq*32 + lane];
            acc0.x += al[hq]     * v0.x;  acc0.y += al[hq]     * v0.y;
            acc1.x += al[4 + hq] * v1.x;  acc1.y += al[4 + hq] * v1.y;
        }
    }

    // epilogue: + mean_h(b_gat) + res, ELU, write x
    int d0 = lane*2;
    float bg0 = 0.25f*(b_gat[d0]   + b_gat[64 + d0]   + b_gat[128 + d0]   + b_gat[192 + d0]);
    float bg1 = 0.25f*(b_gat[d0+1] + b_gat[64 + d0+1] + b_gat[128 + d0+1] + b_gat[192 + d0+1]);

    const float2* rp0 = (const float2*)&g_res[((size_t)(w*2))*HIDD];
    const float2* rp1 = (const float2*)&g_res[((size_t)(w*2 + 1))*HIDD];
    float2 rv0 = rp0[lane];
    float2 rv1 = rp1[lane];

    float o0x = acc0.x + bg0 + rv0.x;
    float o0y = acc0.y + bg1 + rv0.y;
    float o1x = acc1.x + bg0 + rv1.x;
    float o1y = acc1.y + bg1 + rv1.y;
    o0x = o0x > 0.f ? o0x : expm1f(o0x);
    o0y = o0y > 0.f ? o0y : expm1f(o0y);
    o1x = o1x > 0.f ? o1x : expm1f(o1x);
    o1y = o1y > 0.f ? o1y : expm1f(o1y);

    ((float2*)&g_x[((size_t)(w*2))*HIDD])[lane]     = make_float2(o0x, o0y);
    ((float2*)&g_x[((size_t)(w*2 + 1))*HIDD])[lane] = make_float2(o1x, o1y);
}

// ---------------- decoder: out[b,n,:] = x[n,b,:] @ W_dec + b_dec ----------------
__global__ void dec_k(const float* __restrict__ W_dec, const float* __restrict__ b_dec,
                      float* __restrict__ out) {
    int idx = blockIdx.x * blockDim.x + threadIdx.x;
    if (idx >= NB*OUTD) return;
    int o = idx & 7;
    int nb = idx >> 3;
    int n = nb >> 1, b = nb & 1;
    const float* xr = &g_x[(size_t)nb*HIDD];
    float acc = b_dec[o];
#pragma unroll
    for (int k = 0; k < HIDD; k++) acc += xr[k] * W_dec[k*OUTD + o];
    out[((size_t)b*Nn + n)*OUTD + o] = acc;
}

extern "C" void kernel_launch(void* const* d_in, const int* in_sizes, int n_in,
                              void* d_out, int out_size) {
    const float* h     = (const float*)d_in[0];
    const int*   ei    = (const int*)  d_in[1];
    const float* W_enc = (const float*)d_in[2];
    const float* b_enc = (const float*)d_in[3];
    const float* W_gat = (const float*)d_in[4];
    const float* a_l   = (const float*)d_in[5];
    const float* a_r   = (const float*)d_in[6];
    const float* b_gat = (const float*)d_in[7];
    const float* W_res = (const float*)d_in[8];
    const float* b_res = (const float*)d_in[9];
    const float* W_dec = (const float*)d_in[10];
    const float* b_dec = (const float*)d_in[11];
    float* out = (float*)d_out;

    // CSR build (every call; graph-replay safe)
    zero_k<<<(Nn + 255)/256, 256>>>();
    hist_k<<<(Ee + 255)/256, 256>>>(ei);
    scan_k<<<1, 1024>>>();
    fill_k<<<(Ee + 255)/256, 256>>>(ei);

    enc_k<<<(NB*HIDD + 255)/256, 256>>>(h, W_enc, b_enc);

    for (int it = 0; it < 2; ++it) {
        ft_k<<<NB/FTROWS, 256>>>(W_gat, a_l, a_r, W_res, b_res);
        node_agg_k<<<(Nn*32 + 255)/256, 256>>>(b_gat);
    }

    dec_k<<<(NB*OUTD + 255)/256, 256>>>(W_dec, b_dec, out);
}